// round 16
// baseline (speedup 1.0000x reference)
#include <cuda_runtime.h>
#include <cuda_bf16.h>
#include <math.h>
#include <stddef.h>
#include <stdint.h>

// Problem constants
#define Bc 8
#define Tc 2048
#define Cc 1024
#define Hc 16
#define Nn 64
#define CHUNKc 256
#define NCHUNK (Tc / CHUNKc)
#define BT (Bc * Tc)                 // 16384
#define BTC ((size_t)Bc * Tc * Cc)   // 16,777,216
#define CC2 (Cc * Cc)                // 1,048,576

// ---------------------------------------------------------------------------
// Scratch (device globals)
// ---------------------------------------------------------------------------
__device__ __nv_bfloat16 g_xrh[BTC], g_xrl[BTC];
__device__ __nv_bfloat16 g_xkh[BTC], g_xkl[BTC];
__device__ __nv_bfloat16 g_xvh[BTC], g_xvl[BTC];
__device__ __nv_bfloat16 g_rh[BTC], g_rl[BTC];
__device__ __nv_bfloat16 g_kh[BTC], g_kl[BTC];
__device__ __nv_bfloat16 g_vh[BTC], g_vl[BTC];
__device__ __nv_bfloat16 g_y2h[BTC], g_y2l[BTC];
__device__ __nv_bfloat16 g_Wrh[CC2], g_Wrl[CC2];
__device__ __nv_bfloat16 g_Wkh[CC2], g_Wkl[CC2];
__device__ __nv_bfloat16 g_Wvh[CC2], g_Wvl[CC2];
__device__ __nv_bfloat16 g_Woh[CC2], g_Wol[CC2];

// ---------------------------------------------------------------------------
// Helpers (family-portable: cp.async / ldmatrix / mma.sync / mbarrier)
// ---------------------------------------------------------------------------
__device__ __forceinline__ uint32_t smem_u32(const void* p) {
    uint32_t a;
    asm("{ .reg .u64 t; cvta.to.shared.u64 t, %1; cvt.u32.u64 %0, t; }"
        : "=r"(a) : "l"(p));
    return a;
}

#define CP_ASYNC16(sa, gp) \
    asm volatile("cp.async.cg.shared.global [%0], [%1], 16;" :: "r"(sa), "l"(gp) : "memory")
#define CP_COMMIT() asm volatile("cp.async.commit_group;" ::: "memory")
#define CP_WAIT(n)  asm volatile("cp.async.wait_group %0;" :: "n"(n) : "memory")

#define MBAR_INIT(mb, cnt) \
    asm volatile("mbarrier.init.shared.b64 [%0], %1;" :: "r"(mb), "r"((uint32_t)(cnt)) : "memory")
#define MBAR_ARRIVE(mb) \
    asm volatile("mbarrier.arrive.shared.b64 _, [%0];" :: "r"(mb) : "memory")
#define CP_MBAR_ARRIVE(mb) \
    asm volatile("cp.async.mbarrier.arrive.noinc.shared.b64 [%0];" :: "r"(mb) : "memory")

#define MBAR_WAIT(mb, par) do {                                                  \
    uint32_t _mb = (mb); uint32_t _p = (par); uint32_t _done;                    \
    asm volatile("{\n\t.reg .pred p;\n\t"                                        \
        "mbarrier.try_wait.parity.acquire.cta.shared::cta.b64 p, [%1], %2;\n\t"  \
        "selp.b32 %0, 1, 0, p;\n\t}"                                             \
        : "=r"(_done) : "r"(_mb), "r"(_p) : "memory");                           \
    if (!_done) {                                                                \
        asm volatile("{\n\t.reg .pred P1;\n\t"                                   \
            "WL_%=:\n\t"                                                         \
            "mbarrier.try_wait.parity.acquire.cta.shared::cta.b64 P1, [%0], %1, 0x989680;\n\t" \
            "@P1 bra.uni WD_%=;\n\t"                                             \
            "bra.uni WL_%=;\n\t"                                                 \
            "WD_%=:\n\t}"                                                        \
            :: "r"(_mb), "r"(_p) : "memory");                                    \
    }                                                                            \
} while (0)

#define LDSM4(r0, r1, r2, r3, a)                                              \
    asm volatile("ldmatrix.sync.aligned.m8n8.x4.shared.b16 {%0,%1,%2,%3}, [%4];" \
                 : "=r"(r0), "=r"(r1), "=r"(r2), "=r"(r3) : "r"(a))
#define LDSM4T(r0, r1, r2, r3, a)                                             \
    asm volatile("ldmatrix.sync.aligned.m8n8.x4.trans.shared.b16 {%0,%1,%2,%3}, [%4];" \
                 : "=r"(r0), "=r"(r1), "=r"(r2), "=r"(r3) : "r"(a))

#define MMA(c, a, b0_, b1_)                                                   \
    asm volatile("mma.sync.aligned.m16n8k16.row.col.f32.bf16.bf16.f32 "       \
                 "{%0,%1,%2,%3}, {%4,%5,%6,%7}, {%8,%9}, {%0,%1,%2,%3};"      \
                 : "+f"((c)[0]), "+f"((c)[1]), "+f"((c)[2]), "+f"((c)[3])     \
                 : "r"((a)[0]), "r"((a)[1]), "r"((a)[2]), "r"((a)[3]),        \
                   "r"(b0_), "r"(b1_))

__device__ __forceinline__ void split2(float f, __nv_bfloat16& h, __nv_bfloat16& l) {
    h = __float2bfloat16(f);
    l = __float2bfloat16(f - __bfloat162float(h));
}

// pack 4 floats into hi / lo bf16 quads (one 8B store each)
__device__ __forceinline__ void split4_store(
    __nv_bfloat16* dh, __nv_bfloat16* dl, size_t off,
    float f0, float f1, float f2, float f3)
{
    __nv_bfloat16 h0, l0, h1, l1, h2, l2, h3, l3;
    split2(f0, h0, l0); split2(f1, h1, l1);
    split2(f2, h2, l2); split2(f3, h3, l3);
    __nv_bfloat162 ph0 = {h0, h1}, ph1 = {h2, h3};
    __nv_bfloat162 pl0 = {l0, l1}, pl1 = {l2, l3};
    uint2 uh, ul;
    uh.x = *(uint32_t*)&ph0; uh.y = *(uint32_t*)&ph1;
    ul.x = *(uint32_t*)&pl0; ul.y = *(uint32_t*)&pl1;
    *(uint2*)(dh + off) = uh;
    *(uint2*)(dl + off) = ul;
}

// ---------------------------------------------------------------------------
// Kernel 1: volatility gating + time-shift + maa mixing -> bf16 hi/lo splits
// ---------------------------------------------------------------------------
__global__ __launch_bounds__(256) void prep_kernel(
    const float* __restrict__ x, const float* __restrict__ vol,
    const float* __restrict__ Wvol, const float* __restrict__ bvol,
    const float* __restrict__ mk, const float* __restrict__ mv,
    const float* __restrict__ mr)
{
    size_t idx = ((size_t)blockIdx.x * 256 + threadIdx.x) * 4;
    int c = (int)(idx & (Cc - 1));
    size_t bt = idx >> 10;
    int t = (int)(bt & (Tc - 1));

    float4 wv = *(const float4*)(Wvol + c);
    float4 bb = *(const float4*)(bvol + c);
    float4 xv = *(const float4*)(x + idx);
    float vg = vol[bt];

    float xc0 = xv.x / (1.0f + expf(-(vg * wv.x + bb.x)));
    float xc1 = xv.y / (1.0f + expf(-(vg * wv.y + bb.y)));
    float xc2 = xv.z / (1.0f + expf(-(vg * wv.z + bb.z)));
    float xc3 = xv.w / (1.0f + expf(-(vg * wv.w + bb.w)));

    float xx0 = -xc0, xx1 = -xc1, xx2 = -xc2, xx3 = -xc3;
    if (t > 0) {
        float vp = vol[bt - 1];
        float4 xp = *(const float4*)(x + idx - Cc);
        xx0 += xp.x / (1.0f + expf(-(vp * wv.x + bb.x)));
        xx1 += xp.y / (1.0f + expf(-(vp * wv.y + bb.y)));
        xx2 += xp.z / (1.0f + expf(-(vp * wv.z + bb.z)));
        xx3 += xp.w / (1.0f + expf(-(vp * wv.w + bb.w)));
    }

    float4 m4;
    m4 = *(const float4*)(mk + c);
    split4_store(g_xkh, g_xkl, idx,
                 xc0 + xx0 * m4.x, xc1 + xx1 * m4.y,
                 xc2 + xx2 * m4.z, xc3 + xx3 * m4.w);
    m4 = *(const float4*)(mv + c);
    split4_store(g_xvh, g_xvl, idx,
                 xc0 + xx0 * m4.x, xc1 + xx1 * m4.y,
                 xc2 + xx2 * m4.z, xc3 + xx3 * m4.w);
    m4 = *(const float4*)(mr + c);
    split4_store(g_xrh, g_xrl, idx,
                 xc0 + xx0 * m4.x, xc1 + xx1 * m4.y,
                 xc2 + xx2 * m4.z, xc3 + xx3 * m4.w);
}

// fp32 -> bf16 hi/lo split for all 4 weight matrices in one launch (x4 vec)
__global__ __launch_bounds__(256) void conv4_kernel(
    const float* __restrict__ w0, const float* __restrict__ w1,
    const float* __restrict__ w2, const float* __restrict__ w3)
{
    size_t i = ((size_t)blockIdx.x * 256 + threadIdx.x) * 4;
    float4 v;
    v = *(const float4*)(w0 + i); split4_store(g_Wrh, g_Wrl, i, v.x, v.y, v.z, v.w);
    v = *(const float4*)(w1 + i); split4_store(g_Wkh, g_Wkl, i, v.x, v.y, v.z, v.w);
    v = *(const float4*)(w2 + i); split4_store(g_Wvh, g_Wvl, i, v.x, v.y, v.z, v.w);
    v = *(const float4*)(w3 + i); split4_store(g_Woh, g_Wol, i, v.x, v.y, v.z, v.w);
}

// ---------------------------------------------------------------------------
// Kernel 2: GEMM (bf16x3, mma.sync).  CTA 128x128, BK=16, 8 warps (4m x 2n),
// warp tile 32x64, 4-stage mbarrier ring.  kt UNROLLED BY 2 with paired
// barrier waits (flip-order monotonicity: one full-wait + one empty-wait per
// 2 stages).  2 CTAs/SM.  z-batched: up to 3 GEMMs per launch.
// ---------------------------------------------------------------------------
#define GK 1024
#define GN 1024
#define BK2 16
#define NKI (GK / BK2)             // 64
#define TROW 48
#define TILE_B (128 * TROW)        // 6144
#define STAGE_B (4 * TILE_B)       // 24576
#define NSTG 4
#define SMEM_GEMM (NSTG * STAGE_B + 128)

struct GArgs {
    const __nv_bfloat16 *ah, *al, *bh, *bl;
    float* cf;
    __nv_bfloat16 *ch, *cl;
};

__device__ __forceinline__ void gemm_load_stage(
    uint32_t sbase, const __nv_bfloat16* a0, const __nv_bfloat16* a1,
    const __nv_bfloat16* b0, const __nv_bfloat16* b1, int koff, int tid)
{
    const int row = tid >> 1;
    const int half = tid & 1;
    const __nv_bfloat16* srcs[4] = {a0, a1, b0, b1};
    const uint32_t so = row * TROW + half * 16;
#pragma unroll
    for (int m = 0; m < 4; m++) {
        CP_ASYNC16(sbase + m * TILE_B + so,
                   srcs[m] + (size_t)row * GK + koff + half * 8);
    }
}

template<bool SPLIT>
__global__ __launch_bounds__(256, 2)
void gemm_bf16x3(GArgs ga0, GArgs ga1, GArgs ga2)
{
    extern __shared__ __align__(16) char smem[];
    const uint32_t sb = smem_u32(smem);
    const uint32_t mb_full = sb + NSTG * STAGE_B;
    const uint32_t mb_empty = mb_full + 32;

    const GArgs ga = (blockIdx.z == 0) ? ga0 : (blockIdx.z == 1) ? ga1 : ga2;

    const int tid = threadIdx.x;
    const int wid = tid >> 5;
    const int lane = tid & 31;
    const int wm = wid >> 1;
    const int wn = wid & 1;
    const int bm = blockIdx.y * 128;
    const int bn = blockIdx.x * 128;

    const __nv_bfloat16* a0 = ga.ah + (size_t)bm * GK;
    const __nv_bfloat16* a1 = ga.al + (size_t)bm * GK;
    const __nv_bfloat16* b0 = ga.bh + (size_t)bn * GK;
    const __nv_bfloat16* b1 = ga.bl + (size_t)bn * GK;

    if (tid == 0) {
#pragma unroll
        for (int s = 0; s < NSTG; s++) {
            MBAR_INIT(mb_full + s * 8, 256);
            MBAR_INIT(mb_empty + s * 8, 256);
        }
    }
    __syncthreads();

    float acc[2][8][4];
#pragma unroll
    for (int i = 0; i < 2; i++)
#pragma unroll
        for (int j = 0; j < 8; j++)
#pragma unroll
            for (int q = 0; q < 4; q++) acc[i][j][q] = 0.0f;

    const int lr = lane & 15;
    const int lc = lane >> 4;
    const uint32_t kb = lc * 16;

#pragma unroll
    for (int s = 0; s < 3; s++) {
        gemm_load_stage(sb + s * STAGE_B, a0, a1, b0, b1, s * BK2, tid);
        CP_MBAR_ARRIVE(mb_full + s * 8);
    }

    for (int kt = 0; kt < NKI; kt += 2) {
        // ONE full-wait for both stages: full[kt] flips no later than
        // full[kt+1] (per-thread cp.async arrive sets are nested).
        MBAR_WAIT(mb_full + (((kt + 1) & 3)) * 8, ((kt + 1) >> 2) & 1);

#pragma unroll
        for (int u = 0; u < 2; u++) {
            const int k = kt + u;
            const int cs = k & 3;
            const uint32_t cbase = sb + cs * STAGE_B;
            const uint32_t sAh = cbase;
            const uint32_t sAl = cbase + TILE_B;
            const uint32_t sBh = cbase + 2 * TILE_B;
            const uint32_t sBl = cbase + 3 * TILE_B;

            uint32_t ah[2][4], al[2][4];
#pragma unroll
            for (int am = 0; am < 2; am++) {
                uint32_t roff = (uint32_t)(wm * 32 + am * 16 + lr) * TROW + kb;
                LDSM4(ah[am][0], ah[am][1], ah[am][2], ah[am][3], sAh + roff);
                LDSM4(al[am][0], al[am][1], al[am][2], al[am][3], sAl + roff);
            }

            uint32_t bq[2][4], bu[2][4];
            {
                uint32_t roff0 = (uint32_t)(wn * 64 + lr) * TROW + kb;
                LDSM4(bq[0][0], bq[0][1], bq[0][2], bq[0][3], sBh + roff0);
                LDSM4(bu[0][0], bu[0][1], bu[0][2], bu[0][3], sBl + roff0);
            }
#pragma unroll
            for (int p = 0; p < 4; p++) {
                const int cur = p & 1;
                if (p < 3) {
                    uint32_t roffn = (uint32_t)(wn * 64 + (p + 1) * 16 + lr) * TROW + kb;
                    LDSM4(bq[cur ^ 1][0], bq[cur ^ 1][1], bq[cur ^ 1][2], bq[cur ^ 1][3],
                          sBh + roffn);
                    LDSM4(bu[cur ^ 1][0], bu[cur ^ 1][1], bu[cur ^ 1][2], bu[cur ^ 1][3],
                          sBl + roffn);
                }
#pragma unroll
                for (int am = 0; am < 2; am++) {
                    MMA(acc[am][2 * p],     ah[am], bq[cur][0], bq[cur][2]);
                    MMA(acc[am][2 * p],     ah[am], bu[cur][0], bu[cur][2]);
                    MMA(acc[am][2 * p],     al[am], bq[cur][0], bq[cur][2]);
                    MMA(acc[am][2 * p + 1], ah[am], bq[cur][1], bq[cur][3]);
                    MMA(acc[am][2 * p + 1], ah[am], bu[cur][1], bu[cur][3]);
                    MMA(acc[am][2 * p + 1], al[am], bq[cur][1], bq[cur][3]);
                }
            }
            MBAR_ARRIVE(mb_empty + cs * 8);
        }

        // produce stages kt+3 and kt+4 with ONE empty-wait (slot of kt+4 was
        // consumed THIS iteration -> its empty-flip implies the older one).
        const int j1 = kt + 3, j2 = kt + 4;
        if (j2 < NKI) {
            MBAR_WAIT(mb_empty + (j2 & 3) * 8, ((j2 >> 2) & 1) ^ 1);
            gemm_load_stage(sb + (j1 & 3) * STAGE_B, a0, a1, b0, b1, j1 * BK2, tid);
            CP_MBAR_ARRIVE(mb_full + (j1 & 3) * 8);
            gemm_load_stage(sb + (j2 & 3) * STAGE_B, a0, a1, b0, b1, j2 * BK2, tid);
            CP_MBAR_ARRIVE(mb_full + (j2 & 3) * 8);
        } else if (j1 < NKI) {
            MBAR_WAIT(mb_empty + (j1 & 3) * 8, ((j1 >> 2) & 1) ^ 1);
            gemm_load_stage(sb + (j1 & 3) * STAGE_B, a0, a1, b0, b1, j1 * BK2, tid);
            CP_MBAR_ARRIVE(mb_full + (j1 & 3) * 8);
        }
    }

    const int g = lane >> 2;
    const int cc = (lane & 3) * 2;
#pragma unroll
    for (int am = 0; am < 2; am++)
#pragma unroll
        for (int nt = 0; nt < 8; nt++) {
            int row0 = bm + wm * 32 + am * 16 + g;
            int col = bn + wn * 64 + nt * 8 + cc;
            if (!SPLIT) {
                *(float2*)(ga.cf + (size_t)row0 * GN + col) =
                    make_float2(acc[am][nt][0], acc[am][nt][1]);
                *(float2*)(ga.cf + (size_t)(row0 + 8) * GN + col) =
                    make_float2(acc[am][nt][2], acc[am][nt][3]);
            } else {
                __nv_bfloat16 h0, l0, h1, l1;
                split2(acc[am][nt][0], h0, l0);
                split2(acc[am][nt][1], h1, l1);
                *(__nv_bfloat162*)(ga.ch + (size_t)row0 * GN + col) = {h0, h1};
                *(__nv_bfloat162*)(ga.cl + (size_t)row0 * GN + col) = {l0, l1};
                split2(acc[am][nt][2], h0, l0);
                split2(acc[am][nt][3], h1, l1);
                *(__nv_bfloat162*)(ga.ch + (size_t)(row0 + 8) * GN + col) = {h0, h1};
                *(__nv_bfloat162*)(ga.cl + (size_t)(row0 + 8) * GN + col) = {l0, l1};
            }
        }
}

// ---------------------------------------------------------------------------
// Kernel 3: FUSED attention (R13/R15) + cross-chunk KV/R prefetch:
// KV0(c+1) issued after S-half1 (KV buffers dead), R(c+1) after y's sync.
// ---------------------------------------------------------------------------
#define TR2 144
#define KV_TILE (128 * TR2)
#define R_TILE  (256 * TR2)
#define M_TILE  (64 * TR2)
#define SP_OFF  (4 * KV_TILE + 2 * R_TILE + 2 * M_TILE)   // 165888
#define SP_BYTES (64 * 68 * 4)                            // 17408
#define SMEM_ATT (SP_OFF + SP_BYTES)                      // 183296

__global__ __launch_bounds__(256) void attn_fused(
    const float* __restrict__ td,
    const float* __restrict__ gw, const float* __restrict__ gb)
{
    extern __shared__ __align__(16) char smem[];
    const uint32_t sb = smem_u32(smem);
    const uint32_t sKh = sb, sKl = sb + KV_TILE;
    const uint32_t sVh = sb + 2 * KV_TILE, sVl = sb + 3 * KV_TILE;
    const uint32_t sRh = sb + 4 * KV_TILE, sRl = sRh + R_TILE;
    const uint32_t sMh = sRl + R_TILE, sMl = sMh + M_TILE;
    char* smem_c = smem;
    float* SPf = (float*)(smem + SP_OFF);

    const int bh = blockIdx.x;
    const int b = bh >> 4, h = bh & 15;
    const float w = expf(-expf(td[h]));
    const int tid = threadIdx.x;
    const int wid = tid >> 5;
    const int lane = tid & 31;
    const int wid4 = wid & 3;
    const int grp = wid >> 2;

    const int rA = ((lane >> 4) & 1) * 8 + (lane & 7);
    const int cA = ((lane >> 3) & 1) * 16 + wid4 * 32;
    const int rB = ((lane >> 3) & 1) * 8 + (lane & 7);
    const int cB = ((lane >> 4) & 1) * 16;
    const int tb = wid * 32;
    const int lr = lane & 15;
    const int lc = lane >> 4;
    const int g = lane >> 2;
    const int ccol = (lane & 3) * 2;
    const int r0 = wid4 * 16 + g;

    // per-thread load mapping pieces
    const int kvrow = tid >> 1;
    const int kvcb4 = (tid & 1) * 4;

    float m[8][4];
#pragma unroll
    for (int j = 0; j < 8; j++)
#pragma unroll
        for (int q = 0; q < 4; q++) m[j][q] = 0.0f;

    // prologue: KV0(0) + R(0)
    {
        const size_t grow0 = (size_t)b * Tc;
        const size_t goff = (grow0 + kvrow) * Cc + h * 64 + kvcb4 * 8;
        uint32_t ro = kvrow * TR2 + kvcb4 * 16;
#pragma unroll
        for (int ch = 0; ch < 4; ch++) {
            CP_ASYNC16(sKh + ro + ch * 16, g_kh + goff + ch * 8);
            CP_ASYNC16(sKl + ro + ch * 16, g_kl + goff + ch * 8);
            CP_ASYNC16(sVh + ro + ch * 16, g_vh + goff + ch * 8);
            CP_ASYNC16(sVl + ro + ch * 16, g_vl + goff + ch * 8);
        }
        CP_COMMIT();
        const size_t goffr = (grow0 + tid) * Cc + h * 64;
        uint32_t ror = tid * TR2;
#pragma unroll
        for (int ch = 0; ch < 8; ch++) {
            CP_ASYNC16(sRh + ror + ch * 16, g_rh + goffr + ch * 8);
            CP_ASYNC16(sRl + ror + ch * 16, g_rl + goffr + ch * 8);
        }
        CP_COMMIT();
    }

    for (int c = 0; c < NCHUNK; c++) {
        const size_t grow0 = (size_t)b * Tc + c * CHUNKc;

        CP_WAIT(1);          // KV0(c) ready; R(c) in flight
        __syncthreads();

        float s[8][4];
#pragma unroll
        for (int j = 0; j < 8; j++)
#pragma unroll
            for (int q = 0; q < 4; q++) s[j][q] = 0.0f;

        // ---- S half0 ----
#pragma unroll
        for (int tsl = 0; tsl < 4; tsl++) {
            const int t0 = (grp * 4 + tsl) * 16;
            uint32_t aoff = (uint32_t)(t0 + rA) * TR2 + cA;
            uint32_t ah[4], al[4];
            LDSM4T(ah[0], ah[1], ah[2], ah[3], sKh + aoff);
            LDSM4T(al[0], al[1], al[2], al[3], sKl + aoff);
#pragma unroll
            for (int p = 0; p < 4; p++) {
                uint32_t boff = (uint32_t)(t0 + rB) * TR2 + cB + p * 32;
                uint32_t q0, q1, q2, q3, u0, u1, u2, u3;
                LDSM4T(q0, q1, q2, q3, sVh + boff);
                LDSM4T(u0, u1, u2, u3, sVl + boff);
                MMA(s[2 * p],     ah, q0, q1);
                MMA(s[2 * p],     ah, u0, u1);
                MMA(s[2 * p],     al, q0, q1);
                MMA(s[2 * p + 1], ah, q2, q3);
                MMA(s[2 * p + 1], ah, u2, u3);
                MMA(s[2 * p + 1], al, q2, q3);
            }
        }
        __syncthreads();     // done reading KV half0

        // KV half1(c)
        {
            const size_t goff = (grow0 + 128 + kvrow) * Cc + h * 64 + kvcb4 * 8;
            uint32_t ro = kvrow * TR2 + kvcb4 * 16;
#pragma unroll
            for (int ch = 0; ch < 4; ch++) {
                CP_ASYNC16(sKh + ro + ch * 16, g_kh + goff + ch * 8);
                CP_ASYNC16(sKl + ro + ch * 16, g_kl + goff + ch * 8);
                CP_ASYNC16(sVh + ro + ch * 16, g_vh + goff + ch * 8);
                CP_ASYNC16(sVl + ro + ch * 16, g_vl + goff + ch * 8);
            }
        }
        CP_COMMIT();
        CP_WAIT(0);          // R(c) + KV1(c) ready
        __syncthreads();

        // ---- S half1 (accumulate) ----
#pragma unroll
        for (int tsl = 0; tsl < 4; tsl++) {
            const int t0 = (grp * 4 + tsl) * 16;
            uint32_t aoff = (uint32_t)(t0 + rA) * TR2 + cA;
            uint32_t ah[4], al[4];
            LDSM4T(ah[0], ah[1], ah[2], ah[3], sKh + aoff);
            LDSM4T(al[0], al[1], al[2], al[3], sKl + aoff);
#pragma unroll
            for (int p = 0; p < 4; p++) {
                uint32_t boff = (uint32_t)(t0 + rB) * TR2 + cB + p * 32;
                uint32_t q0, q1, q2, q3, u0, u1, u2, u3;
                LDSM4T(q0, q1, q2, q3, sVh + boff);
                LDSM4T(u0, u1, u2, u3, sVl + boff);
                MMA(s[2 * p],     ah, q0, q1);
                MMA(s[2 * p],     ah, u0, u1);
                MMA(s[2 * p],     al, q0, q1);
                MMA(s[2 * p + 1], ah, q2, q3);
                MMA(s[2 * p + 1], ah, u2, u3);
                MMA(s[2 * p + 1], al, q2, q3);
            }
        }

        if (grp == 1) {
#pragma unroll
            for (int ng = 0; ng < 8; ng++) {
                const int col = ng * 8 + ccol;
                *(float2*)(SPf + r0 * 68 + col) = make_float2(s[ng][0], s[ng][1]);
                *(float2*)(SPf + (r0 + 8) * 68 + col) = make_float2(s[ng][2], s[ng][3]);
            }
        }
        __syncthreads();     // all warps done with KV + SP visible

        // ---- prefetch KV0(c+1) into the now-dead KV buffers ----
        if (c + 1 < NCHUNK) {
            const size_t gnext = (size_t)b * Tc + (c + 1) * CHUNKc;
            const size_t goff = (gnext + kvrow) * Cc + h * 64 + kvcb4 * 8;
            uint32_t ro = kvrow * TR2 + kvcb4 * 16;
#pragma unroll
            for (int ch = 0; ch < 4; ch++) {
                CP_ASYNC16(sKh + ro + ch * 16, g_kh + goff + ch * 8);
                CP_ASYNC16(sKl + ro + ch * 16, g_kl + goff + ch * 8);
                CP_ASYNC16(sVh + ro + ch * 16, g_vh + goff + ch * 8);
                CP_ASYNC16(sVl + ro + ch * 16, g_vl + goff + ch * 8);
            }
            CP_COMMIT();
        }

        if (grp == 0) {
            const uint32_t mh_off = (uint32_t)(4 * KV_TILE + 2 * R_TILE);
            const uint32_t ml_off = mh_off + M_TILE;
#pragma unroll
            for (int ng = 0; ng < 8; ng++) {
                const int col = ng * 8 + ccol;
                float2 p0 = *(const float2*)(SPf + r0 * 68 + col);
                float2 p1 = *(const float2*)(SPf + (r0 + 8) * 68 + col);
                __nv_bfloat16 h0, l0, h1, l1;
                m[ng][0] = (s[ng][0] + p0.x) + w * m[ng][0];
                m[ng][1] = (s[ng][1] + p0.y) + w * m[ng][1];
                m[ng][2] = (s[ng][2] + p1.x) + w * m[ng][2];
                m[ng][3] = (s[ng][3] + p1.y) + w * m[ng][3];
                split2(m[ng][0], h0, l0);
                split2(m[ng][1], h1, l1);
                *(__nv_bfloat162*)(smem_c + mh_off + r0 * TR2 + col * 2) = {h0, h1};
                *(__nv_bfloat162*)(smem_c + ml_off + r0 * TR2 + col * 2) = {l0, l1};
                split2(m[ng][2], h0, l0);
                split2(m[ng][3], h1, l1);
                *(__nv_bfloat162*)(smem_c + mh_off + (r0 + 8) * TR2 + col * 2) = {h0, h1};
                *(__nv_bfloat162*)(smem_c + ml_off + (r0 + 8) * TR2 + col * 2) = {l0, l1};
            }
        }
        __syncthreads();     // M visible to all warps

        // ---- y = R @ M : 8 warps x 32 rows ----
        float ya[2][8][4];
#pragma unroll
        for (int i = 0; i < 2; i++)
#pragma unroll
            for (int j = 0; j < 8; j++)
#pragma unroll
                for (int q = 0; q < 4; q++) ya[i][j][q] = 0.0f;

#pragma unroll
        for (int kn = 0; kn < 4; kn++) {
            uint32_t ah[2][4], al[2][4];
#pragma unroll
            for (int am = 0; am < 2; am++) {
                uint32_t roff = (uint32_t)(tb + am * 16 + lr) * TR2 + lc * 16 + kn * 32;
                LDSM4(ah[am][0], ah[am][1], ah[am][2], ah[am][3], sRh + roff);
                LDSM4(al[am][0], al[am][1], al[am][2], al[am][3], sRl + roff);
            }
#pragma unroll
            for (int p = 0; p < 4; p++) {
                uint32_t boff = (uint32_t)(kn * 16 + rB) * TR2 + cB + p * 32;
                uint32_t q0, q1, q2, q3, u0, u1, u2, u3;
                LDSM4T(q0, q1, q2, q3, sMh + boff);
                LDSM4T(u0, u1, u2, u3, sMl + boff);
#pragma unroll
                for (int am = 0; am < 2; am++) {
                    MMA(ya[am][2 * p],     ah[am], q0, q1);
                    MMA(ya[am][2 * p],     ah[am], u0, u1);
                    MMA(ya[am][2 * p],     al[am], q0, q1);
                    MMA(ya[am][2 * p + 1], ah[am], q2, q3);
                    MMA(ya[am][2 * p + 1], ah[am], u2, u3);
                    MMA(ya[am][2 * p + 1], al[am], q2, q3);
                }
            }
        }
        __syncthreads();     // R reads done

        // ---- prefetch R(c+1) into the now-dead R buffers ----
        if (c + 1 < NCHUNK) {
            const size_t gnext = (size_t)b * Tc + (c + 1) * CHUNKc;
            const size_t goffr = (gnext + tid) * Cc + h * 64;
            uint32_t ror = tid * TR2;
#pragma unroll
            for (int ch = 0; ch < 8; ch++) {
                CP_ASYNC16(sRh + ror + ch * 16, g_rh + goffr + ch * 8);
                CP_ASYNC16(sRl + ror + ch * 16, g_rl + goffr + ch * 8);
            }
            CP_COMMIT();
        }

        // ---- fused GroupNorm epilogue -> g_y2 splits ----
#pragma unroll
        for (int am = 0; am < 2; am++) {
            float s1 = 0.f, q1s = 0.f, s2 = 0.f, q2s = 0.f;
#pragma unroll
            for (int ng = 0; ng < 8; ng++) {
                float v0 = w * ya[am][ng][0], v1 = w * ya[am][ng][1];
                float v2 = w * ya[am][ng][2], v3 = w * ya[am][ng][3];
                ya[am][ng][0] = v0; ya[am][ng][1] = v1;
                ya[am][ng][2] = v2; ya[am][ng][3] = v3;
                s1 += v0 + v1; q1s += v0 * v0 + v1 * v1;
                s2 += v2 + v3; q2s += v2 * v2 + v3 * v3;
            }
#pragma unroll
            for (int o = 1; o <= 2; o <<= 1) {
                s1 += __shfl_xor_sync(0xffffffffu, s1, o);
                q1s += __shfl_xor_sync(0xffffffffu, q1s, o);
                s2 += __shfl_xor_sync(0xffffffffu, s2, o);
                q2s += __shfl_xor_sync(0xffffffffu, q2s, o);
            }
            float mean1 = s1 * (1.0f / 64.0f);
            float rstd1 = rsqrtf(q1s * (1.0f / 64.0f) - mean1 * mean1 + 1e-5f);
            float mean2 = s2 * (1.0f / 64.0f);
            float rstd2 = rsqrtf(q2s * (1.0f / 64.0f) - mean2 * mean2 + 1e-5f);

            const int r1 = c * CHUNKc + tb + am * 16 + g;
            const size_t rg1 = (size_t)(b * Tc + r1) * Cc + h * 64;
#pragma unroll
            for (int ng = 0; ng < 8; ng++) {
                int col = ng * 8 + ccol;
                float2 gwv = *(const float2*)(gw + h * 64 + col);
                float2 gbv = *(const float2*)(gb + h * 64 + col);
                __nv_bfloat16 h0, l0, h1, l1;
                split2((ya[am][ng][0] - mean1) * rstd1 * gwv.x + gbv.x, h0, l0);
                split2((ya[am][ng][1] - mean1) * rstd1 * gwv.y + gbv.y, h1, l1);
                *(__nv_bfloat162*)(g_y2h + rg1 + col) = {h0, h1};
                *(__nv_bfloat162*)(g_y2l + rg1 + col) = {l0, l1};
                split2((ya[am][ng][2] - mean2) * rstd2 * gwv.x + gbv.x, h0, l0);
                split2((ya[am][ng][3] - mean2) * rstd2 * gwv.y + gbv.y, h1, l1);
                *(__nv_bfloat162*)(g_y2h + rg1 + 8 * Cc + col) = {h0, h1};
                *(__nv_bfloat162*)(g_y2l + rg1 + 8 * Cc + col) = {l0, l1};
            }
        }
    }
}

// ---------------------------------------------------------------------------
// Host launcher
// ---------------------------------------------------------------------------
extern "C" void kernel_launch(void* const* d_in, const int* in_sizes, int n_in,
                              void* d_out, int out_size)
{
    const float* x    = (const float*)d_in[0];
    const float* vol  = (const float*)d_in[1];
    const float* Wvol = (const float*)d_in[2];
    const float* bvol = (const float*)d_in[3];
    const float* mk   = (const float*)d_in[4];
    const float* mv   = (const float*)d_in[5];
    const float* mr   = (const float*)d_in[6];
    const float* td   = (const float*)d_in[7];
    const float* Wk   = (const float*)d_in[8];
    const float* Wv   = (const float*)d_in[9];
    const float* Wr   = (const float*)d_in[10];
    const float* Wo   = (const float*)d_in[11];
    const float* gw   = (const float*)d_in[12];
    const float* gb   = (const float*)d_in[13];
    float* out = (float*)d_out;

    __nv_bfloat16 *xrh, *xrl, *xkh, *xkl, *xvh, *xvl, *y2h, *y2l;
    __nv_bfloat16 *rh, *rl, *kh, *kl, *vh, *vl;
    __nv_bfloat16 *wrh, *wrl, *wkh, *wkl, *wvh, *wvl, *woh, *wol;
    cudaGetSymbolAddress((void**)&xrh, g_xrh); cudaGetSymbolAddress((void**)&xrl, g_xrl);
    cudaGetSymbolAddress((void**)&xkh, g_xkh); cudaGetSymbolAddress((void**)&xkl, g_xkl);
    cudaGetSymbolAddress((void**)&xvh, g_xvh); cudaGetSymbolAddress((void**)&xvl, g_xvl);
    cudaGetSymbolAddress((void**)&y2h, g_y2h); cudaGetSymbolAddress((void**)&y2l, g_y2l);
    cudaGetSymbolAddress((void**)&rh, g_rh); cudaGetSymbolAddress((void**)&rl, g_rl);
    cudaGetSymbolAddress((void**)&kh, g_kh); cudaGetSymbolAddress((void**)&kl, g_kl);
    cudaGetSymbolAddress((void**)&vh, g_vh); cudaGetSymbolAddress((void**)&vl, g_vl);
    cudaGetSymbolAddress((void**)&wrh, g_Wrh); cudaGetSymbolAddress((void**)&wrl, g_Wrl);
    cudaGetSymbolAddress((void**)&wkh, g_Wkh); cudaGetSymbolAddress((void**)&wkl, g_Wkl);
    cudaGetSymbolAddress((void**)&wvh, g_Wvh); cudaGetSymbolAddress((void**)&wvl, g_Wvl);
    cudaGetSymbolAddress((void**)&woh, g_Woh); cudaGetSymbolAddress((void**)&wol, g_Wol);

    // prep + weight splits (x4 vectorized)
    prep_kernel<<<(unsigned)(BTC / 1024), 256>>>(x, vol, Wvol, bvol, mk, mv, mr);
    conv4_kernel<<<CC2 / 1024, 256>>>(Wr, Wk, Wv, Wo);

    // r/k/v projections, batched into ONE launch (grid.z = 3)
    cudaFuncSetAttribute(gemm_bf16x3<true>,
                         cudaFuncAttributeMaxDynamicSharedMemorySize, SMEM_GEMM);
    cudaFuncSetAttribute(gemm_bf16x3<false>,
                         cudaFuncAttributeMaxDynamicSharedMemorySize, SMEM_GEMM);
    GArgs gr = {xrh, xrl, wrh, wrl, nullptr, rh, rl};
    GArgs gk = {xkh, xkl, wkh, wkl, nullptr, kh, kl};
    GArgs gv = {xvh, xvl, wvh, wvl, nullptr, vh, vl};
    dim3 gg3(GN / 128, BT / 128, 3);
    gemm_bf16x3<true><<<gg3, 256, SMEM_GEMM>>>(gr, gk, gv);

    // fused attention (S + scan + y + GroupNorm), 8 warps/CTA
    cudaFuncSetAttribute(attn_fused, cudaFuncAttributeMaxDynamicSharedMemorySize,
                         SMEM_ATT);
    attn_fused<<<Bc * Hc, 256, SMEM_ATT>>>(td, gw, gb);

    // output projection (fp32 out)
    GArgs go = {y2h, y2l, woh, wol, out, nullptr, nullptr};
    dim3 gg1(GN / 128, BT / 128, 1);
    gemm_bf16x3<false><<<gg1, 256, SMEM_GEMM>>>(go, go, go);
}

// round 17
// speedup vs baseline: 1.2260x; 1.2260x over previous
#include <cuda_runtime.h>
#include <cuda_bf16.h>
#include <math.h>
#include <stddef.h>
#include <stdint.h>

// Problem constants
#define Bc 8
#define Tc 2048
#define Cc 1024
#define Hc 16
#define Nn 64
#define CHUNKc 256
#define NCHUNK (Tc / CHUNKc)
#define BT (Bc * Tc)                 // 16384
#define BTC ((size_t)Bc * Tc * Cc)   // 16,777,216
#define CC2 (Cc * Cc)                // 1,048,576

// ---------------------------------------------------------------------------
// Scratch (device globals)
// ---------------------------------------------------------------------------
__device__ __nv_bfloat16 g_xrh[BTC], g_xrl[BTC];
__device__ __nv_bfloat16 g_xkh[BTC], g_xkl[BTC];
__device__ __nv_bfloat16 g_xvh[BTC], g_xvl[BTC];
__device__ __nv_bfloat16 g_rh[BTC], g_rl[BTC];
__device__ __nv_bfloat16 g_kh[BTC], g_kl[BTC];
__device__ __nv_bfloat16 g_vh[BTC], g_vl[BTC];
__device__ __nv_bfloat16 g_y2h[BTC], g_y2l[BTC];
__device__ __nv_bfloat16 g_Wrh[CC2], g_Wrl[CC2];
__device__ __nv_bfloat16 g_Wkh[CC2], g_Wkl[CC2];
__device__ __nv_bfloat16 g_Wvh[CC2], g_Wvl[CC2];
__device__ __nv_bfloat16 g_Woh[CC2], g_Wol[CC2];

// ---------------------------------------------------------------------------
// Helpers (family-portable: cp.async / ldmatrix / mma.sync / mbarrier)
// ---------------------------------------------------------------------------
__device__ __forceinline__ uint32_t smem_u32(const void* p) {
    uint32_t a;
    asm("{ .reg .u64 t; cvta.to.shared.u64 t, %1; cvt.u32.u64 %0, t; }"
        : "=r"(a) : "l"(p));
    return a;
}

#define CP_ASYNC16(sa, gp) \
    asm volatile("cp.async.cg.shared.global [%0], [%1], 16;" :: "r"(sa), "l"(gp) : "memory")
#define CP_COMMIT() asm volatile("cp.async.commit_group;" ::: "memory")
#define CP_WAIT(n)  asm volatile("cp.async.wait_group %0;" :: "n"(n) : "memory")

#define MBAR_INIT(mb, cnt) \
    asm volatile("mbarrier.init.shared.b64 [%0], %1;" :: "r"(mb), "r"((uint32_t)(cnt)) : "memory")
#define MBAR_ARRIVE(mb) \
    asm volatile("mbarrier.arrive.shared.b64 _, [%0];" :: "r"(mb) : "memory")
#define CP_MBAR_ARRIVE(mb) \
    asm volatile("cp.async.mbarrier.arrive.noinc.shared.b64 [%0];" :: "r"(mb) : "memory")

#define MBAR_WAIT(mb, par) do {                                                  \
    uint32_t _mb = (mb); uint32_t _p = (par); uint32_t _done;                    \
    asm volatile("{\n\t.reg .pred p;\n\t"                                        \
        "mbarrier.try_wait.parity.acquire.cta.shared::cta.b64 p, [%1], %2;\n\t"  \
        "selp.b32 %0, 1, 0, p;\n\t}"                                             \
        : "=r"(_done) : "r"(_mb), "r"(_p) : "memory");                           \
    if (!_done) {                                                                \
        asm volatile("{\n\t.reg .pred P1;\n\t"                                   \
            "WL_%=:\n\t"                                                         \
            "mbarrier.try_wait.parity.acquire.cta.shared::cta.b64 P1, [%0], %1, 0x989680;\n\t" \
            "@P1 bra.uni WD_%=;\n\t"                                             \
            "bra.uni WL_%=;\n\t"                                                 \
            "WD_%=:\n\t}"                                                        \
            :: "r"(_mb), "r"(_p) : "memory");                                    \
    }                                                                            \
} while (0)

#define LDSM4(r0, r1, r2, r3, a)                                              \
    asm volatile("ldmatrix.sync.aligned.m8n8.x4.shared.b16 {%0,%1,%2,%3}, [%4];" \
                 : "=r"(r0), "=r"(r1), "=r"(r2), "=r"(r3) : "r"(a))
#define LDSM4T(r0, r1, r2, r3, a)                                             \
    asm volatile("ldmatrix.sync.aligned.m8n8.x4.trans.shared.b16 {%0,%1,%2,%3}, [%4];" \
                 : "=r"(r0), "=r"(r1), "=r"(r2), "=r"(r3) : "r"(a))

#define MMA(c, a, b0_, b1_)                                                   \
    asm volatile("mma.sync.aligned.m16n8k16.row.col.f32.bf16.bf16.f32 "       \
                 "{%0,%1,%2,%3}, {%4,%5,%6,%7}, {%8,%9}, {%0,%1,%2,%3};"      \
                 : "+f"((c)[0]), "+f"((c)[1]), "+f"((c)[2]), "+f"((c)[3])     \
                 : "r"((a)[0]), "r"((a)[1]), "r"((a)[2]), "r"((a)[3]),        \
                   "r"(b0_), "r"(b1_))

__device__ __forceinline__ void split2(float f, __nv_bfloat16& h, __nv_bfloat16& l) {
    h = __float2bfloat16(f);
    l = __float2bfloat16(f - __bfloat162float(h));
}

// pack 4 floats into hi / lo bf16 quads (one 8B store each)
__device__ __forceinline__ void split4_store(
    __nv_bfloat16* dh, __nv_bfloat16* dl, size_t off,
    float f0, float f1, float f2, float f3)
{
    __nv_bfloat16 h0, l0, h1, l1, h2, l2, h3, l3;
    split2(f0, h0, l0); split2(f1, h1, l1);
    split2(f2, h2, l2); split2(f3, h3, l3);
    __nv_bfloat162 ph0 = {h0, h1}, ph1 = {h2, h3};
    __nv_bfloat162 pl0 = {l0, l1}, pl1 = {l2, l3};
    uint2 uh, ul;
    uh.x = *(uint32_t*)&ph0; uh.y = *(uint32_t*)&ph1;
    ul.x = *(uint32_t*)&pl0; ul.y = *(uint32_t*)&pl1;
    *(uint2*)(dh + off) = uh;
    *(uint2*)(dl + off) = ul;
}

// ---------------------------------------------------------------------------
// Kernel 1: volatility gating + time-shift + maa mixing -> bf16 hi/lo splits
// ---------------------------------------------------------------------------
__global__ __launch_bounds__(256) void prep_kernel(
    const float* __restrict__ x, const float* __restrict__ vol,
    const float* __restrict__ Wvol, const float* __restrict__ bvol,
    const float* __restrict__ mk, const float* __restrict__ mv,
    const float* __restrict__ mr)
{
    size_t idx = ((size_t)blockIdx.x * 256 + threadIdx.x) * 4;
    int c = (int)(idx & (Cc - 1));
    size_t bt = idx >> 10;
    int t = (int)(bt & (Tc - 1));

    float4 wv = *(const float4*)(Wvol + c);
    float4 bb = *(const float4*)(bvol + c);
    float4 xv = *(const float4*)(x + idx);
    float vg = vol[bt];

    float xc0 = xv.x / (1.0f + expf(-(vg * wv.x + bb.x)));
    float xc1 = xv.y / (1.0f + expf(-(vg * wv.y + bb.y)));
    float xc2 = xv.z / (1.0f + expf(-(vg * wv.z + bb.z)));
    float xc3 = xv.w / (1.0f + expf(-(vg * wv.w + bb.w)));

    float xx0 = -xc0, xx1 = -xc1, xx2 = -xc2, xx3 = -xc3;
    if (t > 0) {
        float vp = vol[bt - 1];
        float4 xp = *(const float4*)(x + idx - Cc);
        xx0 += xp.x / (1.0f + expf(-(vp * wv.x + bb.x)));
        xx1 += xp.y / (1.0f + expf(-(vp * wv.y + bb.y)));
        xx2 += xp.z / (1.0f + expf(-(vp * wv.z + bb.z)));
        xx3 += xp.w / (1.0f + expf(-(vp * wv.w + bb.w)));
    }

    float4 m4;
    m4 = *(const float4*)(mk + c);
    split4_store(g_xkh, g_xkl, idx,
                 xc0 + xx0 * m4.x, xc1 + xx1 * m4.y,
                 xc2 + xx2 * m4.z, xc3 + xx3 * m4.w);
    m4 = *(const float4*)(mv + c);
    split4_store(g_xvh, g_xvl, idx,
                 xc0 + xx0 * m4.x, xc1 + xx1 * m4.y,
                 xc2 + xx2 * m4.z, xc3 + xx3 * m4.w);
    m4 = *(const float4*)(mr + c);
    split4_store(g_xrh, g_xrl, idx,
                 xc0 + xx0 * m4.x, xc1 + xx1 * m4.y,
                 xc2 + xx2 * m4.z, xc3 + xx3 * m4.w);
}

// fp32 -> bf16 hi/lo split for all 4 weight matrices in one launch (x4 vec)
__global__ __launch_bounds__(256) void conv4_kernel(
    const float* __restrict__ w0, const float* __restrict__ w1,
    const float* __restrict__ w2, const float* __restrict__ w3)
{
    size_t i = ((size_t)blockIdx.x * 256 + threadIdx.x) * 4;
    float4 v;
    v = *(const float4*)(w0 + i); split4_store(g_Wrh, g_Wrl, i, v.x, v.y, v.z, v.w);
    v = *(const float4*)(w1 + i); split4_store(g_Wkh, g_Wkl, i, v.x, v.y, v.z, v.w);
    v = *(const float4*)(w2 + i); split4_store(g_Wvh, g_Wvl, i, v.x, v.y, v.z, v.w);
    v = *(const float4*)(w3 + i); split4_store(g_Woh, g_Wol, i, v.x, v.y, v.z, v.w);
}

// ---------------------------------------------------------------------------
// Kernel 2: GEMM (R12/R15 winner, EXACT revert): CTA 128x128, BK=16, 8 warps
// (4m x 2n), warp tile 32x64, 4-stage mbarrier ring with per-kt single waits
// (never wait on a barrier whose flip depends on same-iteration peers).
// 2 CTAs/SM.  z-batched: up to 3 GEMMs per launch.
// ---------------------------------------------------------------------------
#define GK 1024
#define GN 1024
#define BK2 16
#define NKI (GK / BK2)             // 64
#define TROW 48
#define TILE_B (128 * TROW)        // 6144
#define STAGE_B (4 * TILE_B)       // 24576
#define NSTG 4
#define SMEM_GEMM (NSTG * STAGE_B + 128)

struct GArgs {
    const __nv_bfloat16 *ah, *al, *bh, *bl;
    float* cf;
    __nv_bfloat16 *ch, *cl;
};

__device__ __forceinline__ void gemm_load_stage(
    uint32_t sbase, const __nv_bfloat16* a0, const __nv_bfloat16* a1,
    const __nv_bfloat16* b0, const __nv_bfloat16* b1, int koff, int tid)
{
    const int row = tid >> 1;
    const int half = tid & 1;
    const __nv_bfloat16* srcs[4] = {a0, a1, b0, b1};
    const uint32_t so = row * TROW + half * 16;
#pragma unroll
    for (int m = 0; m < 4; m++) {
        CP_ASYNC16(sbase + m * TILE_B + so,
                   srcs[m] + (size_t)row * GK + koff + half * 8);
    }
}

template<bool SPLIT>
__global__ __launch_bounds__(256, 2)
void gemm_bf16x3(GArgs ga0, GArgs ga1, GArgs ga2)
{
    extern __shared__ __align__(16) char smem[];
    const uint32_t sb = smem_u32(smem);
    const uint32_t mb_full = sb + NSTG * STAGE_B;
    const uint32_t mb_empty = mb_full + 32;

    const GArgs ga = (blockIdx.z == 0) ? ga0 : (blockIdx.z == 1) ? ga1 : ga2;

    const int tid = threadIdx.x;
    const int wid = tid >> 5;
    const int lane = tid & 31;
    const int wm = wid >> 1;
    const int wn = wid & 1;
    const int bm = blockIdx.y * 128;
    const int bn = blockIdx.x * 128;

    const __nv_bfloat16* a0 = ga.ah + (size_t)bm * GK;
    const __nv_bfloat16* a1 = ga.al + (size_t)bm * GK;
    const __nv_bfloat16* b0 = ga.bh + (size_t)bn * GK;
    const __nv_bfloat16* b1 = ga.bl + (size_t)bn * GK;

    if (tid == 0) {
#pragma unroll
        for (int s = 0; s < NSTG; s++) {
            MBAR_INIT(mb_full + s * 8, 256);
            MBAR_INIT(mb_empty + s * 8, 256);
        }
    }
    __syncthreads();

    float acc[2][8][4];
#pragma unroll
    for (int i = 0; i < 2; i++)
#pragma unroll
        for (int j = 0; j < 8; j++)
#pragma unroll
            for (int q = 0; q < 4; q++) acc[i][j][q] = 0.0f;

    const int lr = lane & 15;
    const int lc = lane >> 4;
    const uint32_t kb = lc * 16;

#pragma unroll
    for (int s = 0; s < 3; s++) {
        gemm_load_stage(sb + s * STAGE_B, a0, a1, b0, b1, s * BK2, tid);
        CP_MBAR_ARRIVE(mb_full + s * 8);
    }

    for (int kt = 0; kt < NKI; kt++) {
        const int cs = kt & 3;

        MBAR_WAIT(mb_full + cs * 8, (kt >> 2) & 1);

        const uint32_t cbase = sb + cs * STAGE_B;
        const uint32_t sAh = cbase;
        const uint32_t sAl = cbase + TILE_B;
        const uint32_t sBh = cbase + 2 * TILE_B;
        const uint32_t sBl = cbase + 3 * TILE_B;

        uint32_t ah[2][4], al[2][4];
#pragma unroll
        for (int am = 0; am < 2; am++) {
            uint32_t roff = (uint32_t)(wm * 32 + am * 16 + lr) * TROW + kb;
            LDSM4(ah[am][0], ah[am][1], ah[am][2], ah[am][3], sAh + roff);
            LDSM4(al[am][0], al[am][1], al[am][2], al[am][3], sAl + roff);
        }

        uint32_t bq[2][4], bu[2][4];
        {
            uint32_t roff0 = (uint32_t)(wn * 64 + lr) * TROW + kb;
            LDSM4(bq[0][0], bq[0][1], bq[0][2], bq[0][3], sBh + roff0);
            LDSM4(bu[0][0], bu[0][1], bu[0][2], bu[0][3], sBl + roff0);
        }
#pragma unroll
        for (int p = 0; p < 4; p++) {
            const int cur = p & 1;
            if (p < 3) {
                uint32_t roffn = (uint32_t)(wn * 64 + (p + 1) * 16 + lr) * TROW + kb;
                LDSM4(bq[cur ^ 1][0], bq[cur ^ 1][1], bq[cur ^ 1][2], bq[cur ^ 1][3],
                      sBh + roffn);
                LDSM4(bu[cur ^ 1][0], bu[cur ^ 1][1], bu[cur ^ 1][2], bu[cur ^ 1][3],
                      sBl + roffn);
            }
#pragma unroll
            for (int am = 0; am < 2; am++) {
                MMA(acc[am][2 * p],     ah[am], bq[cur][0], bq[cur][2]);
                MMA(acc[am][2 * p],     ah[am], bu[cur][0], bu[cur][2]);
                MMA(acc[am][2 * p],     al[am], bq[cur][0], bq[cur][2]);
                MMA(acc[am][2 * p + 1], ah[am], bq[cur][1], bq[cur][3]);
                MMA(acc[am][2 * p + 1], ah[am], bu[cur][1], bu[cur][3]);
                MMA(acc[am][2 * p + 1], al[am], bq[cur][1], bq[cur][3]);
            }
        }
        MBAR_ARRIVE(mb_empty + cs * 8);

        const int j = kt + 3;
        if (j < NKI) {
            const int psl = j & 3;
            MBAR_WAIT(mb_empty + psl * 8, ((j >> 2) & 1) ^ 1);
            gemm_load_stage(sb + psl * STAGE_B, a0, a1, b0, b1, j * BK2, tid);
            CP_MBAR_ARRIVE(mb_full + psl * 8);
        }
    }

    const int g = lane >> 2;
    const int cc = (lane & 3) * 2;
#pragma unroll
    for (int am = 0; am < 2; am++)
#pragma unroll
        for (int nt = 0; nt < 8; nt++) {
            int row0 = bm + wm * 32 + am * 16 + g;
            int col = bn + wn * 64 + nt * 8 + cc;
            if (!SPLIT) {
                *(float2*)(ga.cf + (size_t)row0 * GN + col) =
                    make_float2(acc[am][nt][0], acc[am][nt][1]);
                *(float2*)(ga.cf + (size_t)(row0 + 8) * GN + col) =
                    make_float2(acc[am][nt][2], acc[am][nt][3]);
            } else {
                __nv_bfloat16 h0, l0, h1, l1;
                split2(acc[am][nt][0], h0, l0);
                split2(acc[am][nt][1], h1, l1);
                *(__nv_bfloat162*)(ga.ch + (size_t)row0 * GN + col) = {h0, h1};
                *(__nv_bfloat162*)(ga.cl + (size_t)row0 * GN + col) = {l0, l1};
                split2(acc[am][nt][2], h0, l0);
                split2(acc[am][nt][3], h1, l1);
                *(__nv_bfloat162*)(ga.ch + (size_t)(row0 + 8) * GN + col) = {h0, h1};
                *(__nv_bfloat162*)(ga.cl + (size_t)(row0 + 8) * GN + col) = {l0, l1};
            }
        }
}

// ---------------------------------------------------------------------------
// Kernel 3: FUSED attention (R16 version, verified): 256 threads, S split
// across 2 warp groups, register scan state, y 8x32 rows, fused GroupNorm,
// cross-chunk KV0(c+1)/R(c+1) prefetch into dead buffers.
// ---------------------------------------------------------------------------
#define TR2 144
#define KV_TILE (128 * TR2)
#define R_TILE  (256 * TR2)
#define M_TILE  (64 * TR2)
#define SP_OFF  (4 * KV_TILE + 2 * R_TILE + 2 * M_TILE)   // 165888
#define SP_BYTES (64 * 68 * 4)                            // 17408
#define SMEM_ATT (SP_OFF + SP_BYTES)                      // 183296

__global__ __launch_bounds__(256) void attn_fused(
    const float* __restrict__ td,
    const float* __restrict__ gw, const float* __restrict__ gb)
{
    extern __shared__ __align__(16) char smem[];
    const uint32_t sb = smem_u32(smem);
    const uint32_t sKh = sb, sKl = sb + KV_TILE;
    const uint32_t sVh = sb + 2 * KV_TILE, sVl = sb + 3 * KV_TILE;
    const uint32_t sRh = sb + 4 * KV_TILE, sRl = sRh + R_TILE;
    const uint32_t sMh = sRl + R_TILE, sMl = sMh + M_TILE;
    char* smem_c = smem;
    float* SPf = (float*)(smem + SP_OFF);

    const int bh = blockIdx.x;
    const int b = bh >> 4, h = bh & 15;
    const float w = expf(-expf(td[h]));
    const int tid = threadIdx.x;
    const int wid = tid >> 5;
    const int lane = tid & 31;
    const int wid4 = wid & 3;
    const int grp = wid >> 2;

    const int rA = ((lane >> 4) & 1) * 8 + (lane & 7);
    const int cA = ((lane >> 3) & 1) * 16 + wid4 * 32;
    const int rB = ((lane >> 3) & 1) * 8 + (lane & 7);
    const int cB = ((lane >> 4) & 1) * 16;
    const int tb = wid * 32;
    const int lr = lane & 15;
    const int lc = lane >> 4;
    const int g = lane >> 2;
    const int ccol = (lane & 3) * 2;
    const int r0 = wid4 * 16 + g;

    const int kvrow = tid >> 1;
    const int kvcb4 = (tid & 1) * 4;

    float m[8][4];
#pragma unroll
    for (int j = 0; j < 8; j++)
#pragma unroll
        for (int q = 0; q < 4; q++) m[j][q] = 0.0f;

    // prologue: KV0(0) + R(0)
    {
        const size_t grow0 = (size_t)b * Tc;
        const size_t goff = (grow0 + kvrow) * Cc + h * 64 + kvcb4 * 8;
        uint32_t ro = kvrow * TR2 + kvcb4 * 16;
#pragma unroll
        for (int ch = 0; ch < 4; ch++) {
            CP_ASYNC16(sKh + ro + ch * 16, g_kh + goff + ch * 8);
            CP_ASYNC16(sKl + ro + ch * 16, g_kl + goff + ch * 8);
            CP_ASYNC16(sVh + ro + ch * 16, g_vh + goff + ch * 8);
            CP_ASYNC16(sVl + ro + ch * 16, g_vl + goff + ch * 8);
        }
        CP_COMMIT();
        const size_t goffr = (grow0 + tid) * Cc + h * 64;
        uint32_t ror = tid * TR2;
#pragma unroll
        for (int ch = 0; ch < 8; ch++) {
            CP_ASYNC16(sRh + ror + ch * 16, g_rh + goffr + ch * 8);
            CP_ASYNC16(sRl + ror + ch * 16, g_rl + goffr + ch * 8);
        }
        CP_COMMIT();
    }

    for (int c = 0; c < NCHUNK; c++) {
        const size_t grow0 = (size_t)b * Tc + c * CHUNKc;

        CP_WAIT(1);          // KV0(c) ready; R(c) in flight
        __syncthreads();

        float s[8][4];
#pragma unroll
        for (int j = 0; j < 8; j++)
#pragma unroll
            for (int q = 0; q < 4; q++) s[j][q] = 0.0f;

        // ---- S half0 ----
#pragma unroll
        for (int tsl = 0; tsl < 4; tsl++) {
            const int t0 = (grp * 4 + tsl) * 16;
            uint32_t aoff = (uint32_t)(t0 + rA) * TR2 + cA;
            uint32_t ah[4], al[4];
            LDSM4T(ah[0], ah[1], ah[2], ah[3], sKh + aoff);
            LDSM4T(al[0], al[1], al[2], al[3], sKl + aoff);
#pragma unroll
            for (int p = 0; p < 4; p++) {
                uint32_t boff = (uint32_t)(t0 + rB) * TR2 + cB + p * 32;
                uint32_t q0, q1, q2, q3, u0, u1, u2, u3;
                LDSM4T(q0, q1, q2, q3, sVh + boff);
                LDSM4T(u0, u1, u2, u3, sVl + boff);
                MMA(s[2 * p],     ah, q0, q1);
                MMA(s[2 * p],     ah, u0, u1);
                MMA(s[2 * p],     al, q0, q1);
                MMA(s[2 * p + 1], ah, q2, q3);
                MMA(s[2 * p + 1], ah, u2, u3);
                MMA(s[2 * p + 1], al, q2, q3);
            }
        }
        __syncthreads();     // done reading KV half0

        // KV half1(c)
        {
            const size_t goff = (grow0 + 128 + kvrow) * Cc + h * 64 + kvcb4 * 8;
            uint32_t ro = kvrow * TR2 + kvcb4 * 16;
#pragma unroll
            for (int ch = 0; ch < 4; ch++) {
                CP_ASYNC16(sKh + ro + ch * 16, g_kh + goff + ch * 8);
                CP_ASYNC16(sKl + ro + ch * 16, g_kl + goff + ch * 8);
                CP_ASYNC16(sVh + ro + ch * 16, g_vh + goff + ch * 8);
                CP_ASYNC16(sVl + ro + ch * 16, g_vl + goff + ch * 8);
            }
        }
        CP_COMMIT();
        CP_WAIT(0);          // R(c) + KV1(c) ready
        __syncthreads();

        // ---- S half1 (accumulate) ----
#pragma unroll
        for (int tsl = 0; tsl < 4; tsl++) {
            const int t0 = (grp * 4 + tsl) * 16;
            uint32_t aoff = (uint32_t)(t0 + rA) * TR2 + cA;
            uint32_t ah[4], al[4];
            LDSM4T(ah[0], ah[1], ah[2], ah[3], sKh + aoff);
            LDSM4T(al[0], al[1], al[2], al[3], sKl + aoff);
#pragma unroll
            for (int p = 0; p < 4; p++) {
                uint32_t boff = (uint32_t)(t0 + rB) * TR2 + cB + p * 32;
                uint32_t q0, q1, q2, q3, u0, u1, u2, u3;
                LDSM4T(q0, q1, q2, q3, sVh + boff);
                LDSM4T(u0, u1, u2, u3, sVl + boff);
                MMA(s[2 * p],     ah, q0, q1);
                MMA(s[2 * p],     ah, u0, u1);
                MMA(s[2 * p],     al, q0, q1);
                MMA(s[2 * p + 1], ah, q2, q3);
                MMA(s[2 * p + 1], ah, u2, u3);
                MMA(s[2 * p + 1], al, q2, q3);
            }
        }

        if (grp == 1) {
#pragma unroll
            for (int ng = 0; ng < 8; ng++) {
                const int col = ng * 8 + ccol;
                *(float2*)(SPf + r0 * 68 + col) = make_float2(s[ng][0], s[ng][1]);
                *(float2*)(SPf + (r0 + 8) * 68 + col) = make_float2(s[ng][2], s[ng][3]);
            }
        }
        __syncthreads();     // all warps done with KV + SP visible

        // ---- prefetch KV0(c+1) into the now-dead KV buffers ----
        if (c + 1 < NCHUNK) {
            const size_t gnext = (size_t)b * Tc + (c + 1) * CHUNKc;
            const size_t goff = (gnext + kvrow) * Cc + h * 64 + kvcb4 * 8;
            uint32_t ro = kvrow * TR2 + kvcb4 * 16;
#pragma unroll
            for (int ch = 0; ch < 4; ch++) {
                CP_ASYNC16(sKh + ro + ch * 16, g_kh + goff + ch * 8);
                CP_ASYNC16(sKl + ro + ch * 16, g_kl + goff + ch * 8);
                CP_ASYNC16(sVh + ro + ch * 16, g_vh + goff + ch * 8);
                CP_ASYNC16(sVl + ro + ch * 16, g_vl + goff + ch * 8);
            }
            CP_COMMIT();
        }

        if (grp == 0) {
            const uint32_t mh_off = (uint32_t)(4 * KV_TILE + 2 * R_TILE);
            const uint32_t ml_off = mh_off + M_TILE;
#pragma unroll
            for (int ng = 0; ng < 8; ng++) {
                const int col = ng * 8 + ccol;
                float2 p0 = *(const float2*)(SPf + r0 * 68 + col);
                float2 p1 = *(const float2*)(SPf + (r0 + 8) * 68 + col);
                __nv_bfloat16 h0, l0, h1, l1;
                m[ng][0] = (s[ng][0] + p0.x) + w * m[ng][0];
                m[ng][1] = (s[ng][1] + p0.y) + w * m[ng][1];
                m[ng][2] = (s[ng][2] + p1.x) + w * m[ng][2];
                m[ng][3] = (s[ng][3] + p1.y) + w * m[ng][3];
                split2(m[ng][0], h0, l0);
                split2(m[ng][1], h1, l1);
                *(__nv_bfloat162*)(smem_c + mh_off + r0 * TR2 + col * 2) = {h0, h1};
                *(__nv_bfloat162*)(smem_c + ml_off + r0 * TR2 + col * 2) = {l0, l1};
                split2(m[ng][2], h0, l0);
                split2(m[ng][3], h1, l1);
                *(__nv_bfloat162*)(smem_c + mh_off + (r0 + 8) * TR2 + col * 2) = {h0, h1};
                *(__nv_bfloat162*)(smem_c + ml_off + (r0 + 8) * TR2 + col * 2) = {l0, l1};
            }
        }
        __syncthreads();     // M visible to all warps

        // ---- y = R @ M : 8 warps x 32 rows ----
        float ya[2][8][4];
#pragma unroll
        for (int i = 0; i < 2; i++)
#pragma unroll
            for (int j = 0; j < 8; j++)
#pragma unroll
                for (int q = 0; q < 4; q++) ya[i][j][q] = 0.0f;

#pragma unroll
        for (int kn = 0; kn < 4; kn++) {
            uint32_t ah[2][4], al[2][4];
#pragma unroll
            for (int am = 0; am < 2; am++) {
                uint32_t roff = (uint32_t)(tb + am * 16 + lr) * TR2 + lc * 16 + kn * 32;
                LDSM4(ah[am][0], ah[am][1], ah[am][2], ah[am][3], sRh + roff);
                LDSM4(al[am][0], al[am][1], al[am][2], al[am][3], sRl + roff);
            }
#pragma unroll
            for (int p = 0; p < 4; p++) {
                uint32_t boff = (uint32_t)(kn * 16 + rB) * TR2 + cB + p * 32;
                uint32_t q0, q1, q2, q3, u0, u1, u2, u3;
                LDSM4T(q0, q1, q2, q3, sMh + boff);
                LDSM4T(u0, u1, u2, u3, sMl + boff);
#pragma unroll
                for (int am = 0; am < 2; am++) {
                    MMA(ya[am][2 * p],     ah[am], q0, q1);
                    MMA(ya[am][2 * p],     ah[am], u0, u1);
                    MMA(ya[am][2 * p],     al[am], q0, q1);
                    MMA(ya[am][2 * p + 1], ah[am], q2, q3);
                    MMA(ya[am][2 * p + 1], ah[am], u2, u3);
                    MMA(ya[am][2 * p + 1], al[am], q2, q3);
                }
            }
        }
        __syncthreads();     // R reads done

        // ---- prefetch R(c+1) into the now-dead R buffers ----
        if (c + 1 < NCHUNK) {
            const size_t gnext = (size_t)b * Tc + (c + 1) * CHUNKc;
            const size_t goffr = (gnext + tid) * Cc + h * 64;
            uint32_t ror = tid * TR2;
#pragma unroll
            for (int ch = 0; ch < 8; ch++) {
                CP_ASYNC16(sRh + ror + ch * 16, g_rh + goffr + ch * 8);
                CP_ASYNC16(sRl + ror + ch * 16, g_rl + goffr + ch * 8);
            }
            CP_COMMIT();
        }

        // ---- fused GroupNorm epilogue -> g_y2 splits ----
#pragma unroll
        for (int am = 0; am < 2; am++) {
            float s1 = 0.f, q1s = 0.f, s2 = 0.f, q2s = 0.f;
#pragma unroll
            for (int ng = 0; ng < 8; ng++) {
                float v0 = w * ya[am][ng][0], v1 = w * ya[am][ng][1];
                float v2 = w * ya[am][ng][2], v3 = w * ya[am][ng][3];
                ya[am][ng][0] = v0; ya[am][ng][1] = v1;
                ya[am][ng][2] = v2; ya[am][ng][3] = v3;
                s1 += v0 + v1; q1s += v0 * v0 + v1 * v1;
                s2 += v2 + v3; q2s += v2 * v2 + v3 * v3;
            }
#pragma unroll
            for (int o = 1; o <= 2; o <<= 1) {
                s1 += __shfl_xor_sync(0xffffffffu, s1, o);
                q1s += __shfl_xor_sync(0xffffffffu, q1s, o);
                s2 += __shfl_xor_sync(0xffffffffu, s2, o);
                q2s += __shfl_xor_sync(0xffffffffu, q2s, o);
            }
            float mean1 = s1 * (1.0f / 64.0f);
            float rstd1 = rsqrtf(q1s * (1.0f / 64.0f) - mean1 * mean1 + 1e-5f);
            float mean2 = s2 * (1.0f / 64.0f);
            float rstd2 = rsqrtf(q2s * (1.0f / 64.0f) - mean2 * mean2 + 1e-5f);

            const int r1 = c * CHUNKc + tb + am * 16 + g;
            const size_t rg1 = (size_t)(b * Tc + r1) * Cc + h * 64;
#pragma unroll
            for (int ng = 0; ng < 8; ng++) {
                int col = ng * 8 + ccol;
                float2 gwv = *(const float2*)(gw + h * 64 + col);
                float2 gbv = *(const float2*)(gb + h * 64 + col);
                __nv_bfloat16 h0, l0, h1, l1;
                split2((ya[am][ng][0] - mean1) * rstd1 * gwv.x + gbv.x, h0, l0);
                split2((ya[am][ng][1] - mean1) * rstd1 * gwv.y + gbv.y, h1, l1);
                *(__nv_bfloat162*)(g_y2h + rg1 + col) = {h0, h1};
                *(__nv_bfloat162*)(g_y2l + rg1 + col) = {l0, l1};
                split2((ya[am][ng][2] - mean2) * rstd2 * gwv.x + gbv.x, h0, l0);
                split2((ya[am][ng][3] - mean2) * rstd2 * gwv.y + gbv.y, h1, l1);
                *(__nv_bfloat162*)(g_y2h + rg1 + 8 * Cc + col) = {h0, h1};
                *(__nv_bfloat162*)(g_y2l + rg1 + 8 * Cc + col) = {l0, l1};
            }
        }
    }
}

// ---------------------------------------------------------------------------
// Host launcher
// ---------------------------------------------------------------------------
extern "C" void kernel_launch(void* const* d_in, const int* in_sizes, int n_in,
                              void* d_out, int out_size)
{
    const float* x    = (const float*)d_in[0];
    const float* vol  = (const float*)d_in[1];
    const float* Wvol = (const float*)d_in[2];
    const float* bvol = (const float*)d_in[3];
    const float* mk   = (const float*)d_in[4];
    const float* mv   = (const float*)d_in[5];
    const float* mr   = (const float*)d_in[6];
    const float* td   = (const float*)d_in[7];
    const float* Wk   = (const float*)d_in[8];
    const float* Wv   = (const float*)d_in[9];
    const float* Wr   = (const float*)d_in[10];
    const float* Wo   = (const float*)d_in[11];
    const float* gw   = (const float*)d_in[12];
    const float* gb   = (const float*)d_in[13];
    float* out = (float*)d_out;

    __nv_bfloat16 *xrh, *xrl, *xkh, *xkl, *xvh, *xvl, *y2h, *y2l;
    __nv_bfloat16 *rh, *rl, *kh, *kl, *vh, *vl;
    __nv_bfloat16 *wrh, *wrl, *wkh, *wkl, *wvh, *wvl, *woh, *wol;
    cudaGetSymbolAddress((void**)&xrh, g_xrh); cudaGetSymbolAddress((void**)&xrl, g_xrl);
    cudaGetSymbolAddress((void**)&xkh, g_xkh); cudaGetSymbolAddress((void**)&xkl, g_xkl);
    cudaGetSymbolAddress((void**)&xvh, g_xvh); cudaGetSymbolAddress((void**)&xvl, g_xvl);
    cudaGetSymbolAddress((void**)&y2h, g_y2h); cudaGetSymbolAddress((void**)&y2l, g_y2l);
    cudaGetSymbolAddress((void**)&rh, g_rh); cudaGetSymbolAddress((void**)&rl, g_rl);
    cudaGetSymbolAddress((void**)&kh, g_kh); cudaGetSymbolAddress((void**)&kl, g_kl);
    cudaGetSymbolAddress((void**)&vh, g_vh); cudaGetSymbolAddress((void**)&vl, g_vl);
    cudaGetSymbolAddress((void**)&wrh, g_Wrh); cudaGetSymbolAddress((void**)&wrl, g_Wrl);
    cudaGetSymbolAddress((void**)&wkh, g_Wkh); cudaGetSymbolAddress((void**)&wkl, g_Wkl);
    cudaGetSymbolAddress((void**)&wvh, g_Wvh); cudaGetSymbolAddress((void**)&wvl, g_Wvl);
    cudaGetSymbolAddress((void**)&woh, g_Woh); cudaGetSymbolAddress((void**)&wol, g_Wol);

    // prep + weight splits (x4 vectorized)
    prep_kernel<<<(unsigned)(BTC / 1024), 256>>>(x, vol, Wvol, bvol, mk, mv, mr);
    conv4_kernel<<<CC2 / 1024, 256>>>(Wr, Wk, Wv, Wo);

    // r/k/v projections, batched into ONE launch (grid.z = 3)
    cudaFuncSetAttribute(gemm_bf16x3<true>,
                         cudaFuncAttributeMaxDynamicSharedMemorySize, SMEM_GEMM);
    cudaFuncSetAttribute(gemm_bf16x3<false>,
                         cudaFuncAttributeMaxDynamicSharedMemorySize, SMEM_GEMM);
    GArgs gr = {xrh, xrl, wrh, wrl, nullptr, rh, rl};
    GArgs gk = {xkh, xkl, wkh, wkl, nullptr, kh, kl};
    GArgs gv = {xvh, xvl, wvh, wvl, nullptr, vh, vl};
    dim3 gg3(GN / 128, BT / 128, 3);
    gemm_bf16x3<true><<<gg3, 256, SMEM_GEMM>>>(gr, gk, gv);

    // fused attention (S + scan + y + GroupNorm), 8 warps/CTA
    cudaFuncSetAttribute(attn_fused, cudaFuncAttributeMaxDynamicSharedMemorySize,
                         SMEM_ATT);
    attn_fused<<<Bc * Hc, 256, SMEM_ATT>>>(td, gw, gb);

    // output projection (fp32 out)
    GArgs go = {y2h, y2l, woh, wol, out, nullptr, nullptr};
    dim3 gg1(GN / 128, BT / 128, 1);
    gemm_bf16x3<false><<<gg1, 256, SMEM_GEMM>>>(go, go, go);
}